// round 3
// baseline (speedup 1.0000x reference)
#include <cuda_runtime.h>
#include <cstdint>

// Problem constants
#define BB 32
#define SS 512
#define HH 768
#define TT 100
#define THH 512
#define LL 5

// Scratch (static device globals — no allocation)
__device__ float g_scratch[BB * SS * HH];   // GEMM1 output: 50.3 MB
__device__ float g_rbar[BB * HH];           // masked sums of relu(LN(.)) rows

// ---------------------------------------------------------------------------
// Kernel 0: zero the rbar accumulator
// ---------------------------------------------------------------------------
__global__ void zero_rbar_kernel() {
    int i = blockIdx.x * blockDim.x + threadIdx.x;
    if (i < BB * HH) g_rbar[i] = 0.0f;
}

// ---------------------------------------------------------------------------
// Kernel 1: G[b,s,:] = seq[b,s,:] @ W1[lang[b]] + b1[lang[b]]
// Tiled SGEMM, BM=128 BN=128 BK=8, 256 threads, 8x8 microtile.
// M = B*S = 16384 (div 128), N = 768 (div 128), K = 768 (div 8).
// All 128 rows of a block belong to one batch element (512 % 128 == 0).
// ---------------------------------------------------------------------------
__global__ __launch_bounds__(256) void gemm1_kernel(
    const float* __restrict__ seq,
    const float* __restrict__ W1,
    const float* __restrict__ b1,
    const int* __restrict__ lang)
{
    const int BM = 128, BN = 128, BK = 8;
    __shared__ float As[BK][BM];   // transposed A tile
    __shared__ float Bs[BK][BN];

    const int m0 = blockIdx.y * BM;
    const int n0 = blockIdx.x * BN;
    const int b = m0 / SS;
    const int l = lang[b];
    const float* __restrict__ Wl = W1 + (size_t)l * HH * HH;

    const int tid = threadIdx.x;
    const int tx = tid & 15;   // 16 col groups of 8
    const int ty = tid >> 4;   // 16 row groups of 8

    // A-tile load coords: 128 rows x 8 cols = 256 float4 (1 per thread)
    const int a_row = tid >> 1;
    const int a_c4 = (tid & 1) * 4;
    // B-tile load coords: 8 rows x 128 cols = 256 float4 (1 per thread)
    const int b_row = tid >> 5;
    const int b_c4 = (tid & 31) * 4;

    float acc[8][8];
#pragma unroll
    for (int i = 0; i < 8; i++)
#pragma unroll
        for (int j = 0; j < 8; j++) acc[i][j] = 0.0f;

    for (int k0 = 0; k0 < HH; k0 += BK) {
        // Load A tile (transpose on store)
        {
            float4 v = *reinterpret_cast<const float4*>(
                seq + (size_t)(m0 + a_row) * HH + k0 + a_c4);
            As[a_c4 + 0][a_row] = v.x;
            As[a_c4 + 1][a_row] = v.y;
            As[a_c4 + 2][a_row] = v.z;
            As[a_c4 + 3][a_row] = v.w;
        }
        // Load B tile (row-major contiguous)
        {
            float4 v = *reinterpret_cast<const float4*>(
                Wl + (size_t)(k0 + b_row) * HH + n0 + b_c4);
            *reinterpret_cast<float4*>(&Bs[b_row][b_c4]) = v;
        }
        __syncthreads();

#pragma unroll
        for (int k = 0; k < BK; k++) {
            float4 a0 = *reinterpret_cast<const float4*>(&As[k][ty * 8]);
            float4 a1 = *reinterpret_cast<const float4*>(&As[k][ty * 8 + 4]);
            float4 b0 = *reinterpret_cast<const float4*>(&Bs[k][tx * 8]);
            float4 b1v = *reinterpret_cast<const float4*>(&Bs[k][tx * 8 + 4]);
            float a[8] = {a0.x, a0.y, a0.z, a0.w, a1.x, a1.y, a1.z, a1.w};
            float bb[8] = {b0.x, b0.y, b0.z, b0.w, b1v.x, b1v.y, b1v.z, b1v.w};
#pragma unroll
            for (int i = 0; i < 8; i++)
#pragma unroll
                for (int j = 0; j < 8; j++) acc[i][j] += a[i] * bb[j];
        }
        __syncthreads();
    }

    // Epilogue: add b1, write scratch
    const int n = n0 + tx * 8;
    float4 bias0 = *reinterpret_cast<const float4*>(b1 + (size_t)l * HH + n);
    float4 bias1 = *reinterpret_cast<const float4*>(b1 + (size_t)l * HH + n + 4);
#pragma unroll
    for (int i = 0; i < 8; i++) {
        int m = m0 + ty * 8 + i;
        float4 o0, o1;
        o0.x = acc[i][0] + bias0.x;
        o0.y = acc[i][1] + bias0.y;
        o0.z = acc[i][2] + bias0.z;
        o0.w = acc[i][3] + bias0.w;
        o1.x = acc[i][4] + bias1.x;
        o1.y = acc[i][5] + bias1.y;
        o1.z = acc[i][6] + bias1.z;
        o1.w = acc[i][7] + bias1.w;
        *reinterpret_cast<float4*>(g_scratch + (size_t)m * HH + n) = o0;
        *reinterpret_cast<float4*>(g_scratch + (size_t)m * HH + n + 4) = o1;
    }
}

// ---------------------------------------------------------------------------
// Kernel 2: per (b,s) row: LayerNorm over H, ReLU, multiply by mask,
// accumulate into g_rbar[b,:]. Each warp processes 8 rows sequentially,
// accumulating in registers; one shared-atomic pass per warp at the end.
// Grid: BB*8 blocks (each block covers 64 rows of one batch element).
// ---------------------------------------------------------------------------
__global__ __launch_bounds__(256) void ln_relu_pool_kernel(
    const float* __restrict__ mask,
    const int* __restrict__ lang,
    const float* __restrict__ g1,
    const float* __restrict__ be1)
{
    __shared__ float accum[HH];
    const int blk = blockIdx.x;            // 256 blocks
    const int b = blk >> 3;                // 8 blocks per batch element
    const int s_base = (blk & 7) * 64;
    const int tid = threadIdx.x;
    const int w = tid >> 5;
    const int lane = tid & 31;

    for (int c = tid; c < HH; c += 256) accum[c] = 0.0f;
    __syncthreads();

    const int l = lang[b];
    const float* __restrict__ g = g1 + (size_t)l * HH;
    const float* __restrict__ be = be1 + (size_t)l * HH;

    // Cache gamma/beta for this lane's 24 columns
    float gv[24], bev[24];
#pragma unroll
    for (int i = 0; i < 6; i++) {
        float4 gg = *reinterpret_cast<const float4*>(g + i * 128 + lane * 4);
        float4 bb = *reinterpret_cast<const float4*>(be + i * 128 + lane * 4);
        gv[i * 4 + 0] = gg.x; gv[i * 4 + 1] = gg.y;
        gv[i * 4 + 2] = gg.z; gv[i * 4 + 3] = gg.w;
        bev[i * 4 + 0] = bb.x; bev[i * 4 + 1] = bb.y;
        bev[i * 4 + 2] = bb.z; bev[i * 4 + 3] = bb.w;
    }

    float racc[24];
#pragma unroll
    for (int i = 0; i < 24; i++) racc[i] = 0.0f;

    for (int r = 0; r < 8; r++) {
        const int s = s_base + w * 8 + r;
        const float* __restrict__ row = g_scratch + ((size_t)b * SS + s) * HH;

        float x[24];
        float sum = 0.0f, sq = 0.0f;
#pragma unroll
        for (int i = 0; i < 6; i++) {
            float4 v = *reinterpret_cast<const float4*>(row + i * 128 + lane * 4);
            x[i * 4 + 0] = v.x; x[i * 4 + 1] = v.y;
            x[i * 4 + 2] = v.z; x[i * 4 + 3] = v.w;
            sum += v.x + v.y + v.z + v.w;
            sq += v.x * v.x + v.y * v.y + v.z * v.z + v.w * v.w;
        }
#pragma unroll
        for (int o = 16; o > 0; o >>= 1) {
            sum += __shfl_xor_sync(0xffffffffu, sum, o);
            sq  += __shfl_xor_sync(0xffffffffu, sq, o);
        }
        const float mean = sum * (1.0f / HH);
        const float var = sq * (1.0f / HH) - mean * mean;
        const float rstd = rsqrtf(var + 1e-5f);
        const float mk = mask[b * SS + s];

#pragma unroll
        for (int i = 0; i < 24; i++) {
            float v = (x[i] - mean) * rstd * gv[i] + bev[i];
            racc[i] += fmaxf(v, 0.0f) * mk;
        }
    }

    // One shared-atomic pass (conflict degree = 8 warps)
#pragma unroll
    for (int i = 0; i < 6; i++) {
#pragma unroll
        for (int j = 0; j < 4; j++) {
            int c = i * 128 + lane * 4 + j;
            atomicAdd(&accum[c], racc[i * 4 + j]);
        }
    }
    __syncthreads();
    for (int c = tid; c < HH; c += 256)
        atomicAdd(&g_rbar[b * HH + c], accum[c]);
}

// ---------------------------------------------------------------------------
// Kernel 3: per batch element:
//   pooled = (rbar @ W2[l]) / D + (M/D) * b2[l]    (pool commuted past W2)
//   combined = [pooled, lda]
//   fused = LN(combined @ Wf + bf) -> relu -> out
// One block of 256 threads per batch element.
// ---------------------------------------------------------------------------
__global__ __launch_bounds__(256) void tail_kernel(
    const float* __restrict__ mask,
    const int* __restrict__ lang,
    const float* __restrict__ lda,
    const float* __restrict__ W2,
    const float* __restrict__ b2,
    const float* __restrict__ Wf,
    const float* __restrict__ bf,
    const float* __restrict__ gf,
    const float* __restrict__ bef,
    float* __restrict__ out)
{
    const int b = blockIdx.x;
    const int tid = threadIdx.x;
    const int lane = tid & 31;
    const int warp = tid >> 5;
    __shared__ float comb[HH + TT];
    __shared__ float tvec[HH];
    __shared__ float red[32];

    const int l = lang[b];

    // mask sum
    float ms = 0.0f;
    for (int s = tid; s < SS; s += 256) ms += mask[b * SS + s];
#pragma unroll
    for (int o = 16; o > 0; o >>= 1) ms += __shfl_xor_sync(0xffffffffu, ms, o);
    if (lane == 0) red[warp] = ms;
    __syncthreads();
    if (tid < 32) {
        float v = (tid < 8) ? red[tid] : 0.0f;
#pragma unroll
        for (int o = 4; o > 0; o >>= 1) v += __shfl_xor_sync(0xffffffffu, v, o);
        if (tid == 0) red[0] = v;
    }
    __syncthreads();
    const float Mtot = red[0];
    const float invD = 1.0f / (Mtot + 1e-10f);

    for (int c = tid; c < HH; c += 256) tvec[c] = g_rbar[b * HH + c];
    __syncthreads();

    // pooled: 3 output columns per thread
    float acc0 = 0.0f, acc1 = 0.0f, acc2 = 0.0f;
    const float* __restrict__ W2l = W2 + (size_t)l * HH * HH;
#pragma unroll 8
    for (int h = 0; h < HH; h++) {
        const float th = tvec[h];
        const float* __restrict__ wrow = W2l + (size_t)h * HH;
        acc0 += th * wrow[tid];
        acc1 += th * wrow[tid + 256];
        acc2 += th * wrow[tid + 512];
    }
    comb[tid]       = (acc0 + Mtot * b2[l * HH + tid])       * invD;
    comb[tid + 256] = (acc1 + Mtot * b2[l * HH + tid + 256]) * invD;
    comb[tid + 512] = (acc2 + Mtot * b2[l * HH + tid + 512]) * invD;
    for (int i = tid; i < TT; i += 256) comb[HH + i] = lda[b * TT + i];
    __syncthreads();

    // fusion MLP: 2 outputs per thread over (H+T)=868 inputs
    float f0 = 0.0f, f1 = 0.0f;
#pragma unroll 4
    for (int i = 0; i < HH + TT; i++) {
        const float c = comb[i];
        f0 += c * Wf[(size_t)i * THH + tid];
        f1 += c * Wf[(size_t)i * THH + tid + 256];
    }
    f0 += bf[tid];
    f1 += bf[tid + 256];

    // LN over 512
    float sum = f0 + f1;
    float sq = f0 * f0 + f1 * f1;
#pragma unroll
    for (int o = 16; o > 0; o >>= 1) {
        sum += __shfl_xor_sync(0xffffffffu, sum, o);
        sq  += __shfl_xor_sync(0xffffffffu, sq, o);
    }
    if (lane == 0) { red[warp] = sum; red[warp + 8] = sq; }
    __syncthreads();
    if (tid < 32) {
        float v = (tid < 8) ? red[tid] : 0.0f;
        float v2 = (tid < 8) ? red[tid + 8] : 0.0f;
#pragma unroll
        for (int o = 4; o > 0; o >>= 1) {
            v  += __shfl_xor_sync(0xffffffffu, v, o);
            v2 += __shfl_xor_sync(0xffffffffu, v2, o);
        }
        if (tid == 0) { red[0] = v; red[1] = v2; }
    }
    __syncthreads();
    const float mean = red[0] * (1.0f / THH);
    const float var = red[1] * (1.0f / THH) - mean * mean;
    const float rstd = rsqrtf(var + 1e-5f);

    float o0 = (f0 - mean) * rstd * gf[tid] + bef[tid];
    float o1 = (f1 - mean) * rstd * gf[tid + 256] + bef[tid + 256];
    out[b * THH + tid]       = fmaxf(o0, 0.0f);
    out[b * THH + tid + 256] = fmaxf(o1, 0.0f);
}

// ---------------------------------------------------------------------------
extern "C" void kernel_launch(void* const* d_in, const int* in_sizes, int n_in,
                              void* d_out, int out_size)
{
    const float* seq  = (const float*)d_in[0];   // [B,S,H]
    const float* mask = (const float*)d_in[1];   // [B,S]
    const int*   lang = (const int*)d_in[2];     // [B]
    const float* lda  = (const float*)d_in[3];   // [B,T]
    const float* W1   = (const float*)d_in[4];   // [L,H,H]
    const float* b1   = (const float*)d_in[5];   // [L,H]
    const float* g1   = (const float*)d_in[6];   // [L,H]
    const float* be1  = (const float*)d_in[7];   // [L,H]
    const float* W2   = (const float*)d_in[8];   // [L,H,H]
    const float* b2   = (const float*)d_in[9];   // [L,H]
    const float* Wf   = (const float*)d_in[10];  // [H+T,TH]
    const float* bf   = (const float*)d_in[11];  // [TH]
    const float* gf   = (const float*)d_in[12];  // [TH]
    const float* bef  = (const float*)d_in[13];  // [TH]
    float* out = (float*)d_out;                  // [B,TH]

    (void)in_sizes; (void)n_in; (void)out_size;

    zero_rbar_kernel<<<(BB * HH + 255) / 256, 256>>>();
    gemm1_kernel<<<dim3(HH / 128, (BB * SS) / 128), 256>>>(seq, W1, b1, lang);
    ln_relu_pool_kernel<<<BB * 8, 256>>>(mask, lang, g1, be1);
    tail_kernel<<<BB, 256>>>(mask, lang, lda, W2, b2, Wf, bf, gf, bef, out);
}

// round 4
// speedup vs baseline: 1.2375x; 1.2375x over previous
#include <cuda_runtime.h>
#include <cstdint>

// Problem constants
#define BB 32
#define SS 512
#define HH 768
#define TT 100
#define THH 512
#define LL 5

// Scratch (static device globals — no allocation)
__device__ float g_scratch[BB * SS * HH];   // GEMM1 output: 50.3 MB
__device__ float g_rbar[BB * HH];           // masked sums of relu(LN(.)) rows
__device__ float g_msum[BB];                // mask sums
__device__ float g_comb[BB * (HH + TT)];    // [pooled, lda] per batch
__device__ float g_fused[BB * THH];         // pre-LN fusion output

// ---------------------------------------------------------------------------
// Kernel 0: zero rbar + compute per-batch mask sum. Grid BB, block 256.
// ---------------------------------------------------------------------------
__global__ __launch_bounds__(256) void init_kernel(const float* __restrict__ mask) {
    const int b = blockIdx.x;
    const int tid = threadIdx.x;
    const int lane = tid & 31;
    const int warp = tid >> 5;
    __shared__ float red[8];

    for (int c = tid; c < HH; c += 256) g_rbar[b * HH + c] = 0.0f;

    float ms = 0.0f;
    for (int s = tid; s < SS; s += 256) ms += mask[b * SS + s];
#pragma unroll
    for (int o = 16; o > 0; o >>= 1) ms += __shfl_xor_sync(0xffffffffu, ms, o);
    if (lane == 0) red[warp] = ms;
    __syncthreads();
    if (tid == 0) {
        float v = 0.0f;
#pragma unroll
        for (int i = 0; i < 8; i++) v += red[i];
        g_msum[b] = v;
    }
}

// ---------------------------------------------------------------------------
// Kernel 1: G[b,s,:] = seq[b,s,:] @ W1[lang[b]] + b1[lang[b]]
// Tiled SGEMM, BM=128 BN=128 BK=8, 256 threads, 8x8 microtile,
// register double-buffered gmem->smem loads.
// ---------------------------------------------------------------------------
__global__ __launch_bounds__(256) void gemm1_kernel(
    const float* __restrict__ seq,
    const float* __restrict__ W1,
    const float* __restrict__ b1,
    const int* __restrict__ lang)
{
    const int BM = 128, BN = 128, BK = 8;
    __shared__ float As[BK][BM];   // transposed A tile
    __shared__ float Bs[BK][BN];

    const int m0 = blockIdx.y * BM;
    const int n0 = blockIdx.x * BN;
    const int b = m0 / SS;
    const int l = lang[b];
    const float* __restrict__ Wl = W1 + (size_t)l * HH * HH;

    const int tid = threadIdx.x;
    const int tx = tid & 15;   // 16 col groups of 8
    const int ty = tid >> 4;   // 16 row groups of 8

    // A-tile load coords: 128 rows x 8 cols = 256 float4 (1 per thread)
    const int a_row = tid >> 1;
    const int a_c4 = (tid & 1) * 4;
    // B-tile load coords: 8 rows x 128 cols = 256 float4 (1 per thread)
    const int b_row = tid >> 5;
    const int b_c4 = (tid & 31) * 4;

    float acc[8][8];
#pragma unroll
    for (int i = 0; i < 8; i++)
#pragma unroll
        for (int j = 0; j < 8; j++) acc[i][j] = 0.0f;

    // Prologue: fetch first tiles into registers
    float4 ra = *reinterpret_cast<const float4*>(
        seq + (size_t)(m0 + a_row) * HH + a_c4);
    float4 rb = *reinterpret_cast<const float4*>(
        Wl + (size_t)b_row * HH + n0 + b_c4);

    for (int k0 = 0; k0 < HH; k0 += BK) {
        // Commit staged registers to smem
        As[a_c4 + 0][a_row] = ra.x;
        As[a_c4 + 1][a_row] = ra.y;
        As[a_c4 + 2][a_row] = ra.z;
        As[a_c4 + 3][a_row] = ra.w;
        *reinterpret_cast<float4*>(&Bs[b_row][b_c4]) = rb;
        __syncthreads();

        // Prefetch next tiles (overlaps with FFMA loop below)
        if (k0 + BK < HH) {
            ra = *reinterpret_cast<const float4*>(
                seq + (size_t)(m0 + a_row) * HH + k0 + BK + a_c4);
            rb = *reinterpret_cast<const float4*>(
                Wl + (size_t)(k0 + BK + b_row) * HH + n0 + b_c4);
        }

#pragma unroll
        for (int k = 0; k < BK; k++) {
            float4 a0 = *reinterpret_cast<const float4*>(&As[k][ty * 8]);
            float4 a1 = *reinterpret_cast<const float4*>(&As[k][ty * 8 + 4]);
            float4 b0 = *reinterpret_cast<const float4*>(&Bs[k][tx * 8]);
            float4 b1v = *reinterpret_cast<const float4*>(&Bs[k][tx * 8 + 4]);
            float a[8] = {a0.x, a0.y, a0.z, a0.w, a1.x, a1.y, a1.z, a1.w};
            float bb[8] = {b0.x, b0.y, b0.z, b0.w, b1v.x, b1v.y, b1v.z, b1v.w};
#pragma unroll
            for (int i = 0; i < 8; i++)
#pragma unroll
                for (int j = 0; j < 8; j++) acc[i][j] += a[i] * bb[j];
        }
        __syncthreads();
    }

    // Epilogue: add b1, write scratch
    const int n = n0 + tx * 8;
    float4 bias0 = *reinterpret_cast<const float4*>(b1 + (size_t)l * HH + n);
    float4 bias1 = *reinterpret_cast<const float4*>(b1 + (size_t)l * HH + n + 4);
#pragma unroll
    for (int i = 0; i < 8; i++) {
        int m = m0 + ty * 8 + i;
        float4 o0, o1;
        o0.x = acc[i][0] + bias0.x;
        o0.y = acc[i][1] + bias0.y;
        o0.z = acc[i][2] + bias0.z;
        o0.w = acc[i][3] + bias0.w;
        o1.x = acc[i][4] + bias1.x;
        o1.y = acc[i][5] + bias1.y;
        o1.z = acc[i][6] + bias1.z;
        o1.w = acc[i][7] + bias1.w;
        *reinterpret_cast<float4*>(g_scratch + (size_t)m * HH + n) = o0;
        *reinterpret_cast<float4*>(g_scratch + (size_t)m * HH + n + 4) = o1;
    }
}

// ---------------------------------------------------------------------------
// Kernel 2: per (b,s) row: LayerNorm over H, ReLU, multiply by mask,
// accumulate into g_rbar[b,:]. Each warp processes 8 rows sequentially,
// accumulating in registers; one shared-atomic pass per warp at the end.
// ---------------------------------------------------------------------------
__global__ __launch_bounds__(256) void ln_relu_pool_kernel(
    const float* __restrict__ mask,
    const int* __restrict__ lang,
    const float* __restrict__ g1,
    const float* __restrict__ be1)
{
    __shared__ float accum[HH];
    const int blk = blockIdx.x;            // 256 blocks
    const int b = blk >> 3;                // 8 blocks per batch element
    const int s_base = (blk & 7) * 64;
    const int tid = threadIdx.x;
    const int w = tid >> 5;
    const int lane = tid & 31;

    for (int c = tid; c < HH; c += 256) accum[c] = 0.0f;
    __syncthreads();

    const int l = lang[b];
    const float* __restrict__ g = g1 + (size_t)l * HH;
    const float* __restrict__ be = be1 + (size_t)l * HH;

    float gv[24], bev[24];
#pragma unroll
    for (int i = 0; i < 6; i++) {
        float4 gg = *reinterpret_cast<const float4*>(g + i * 128 + lane * 4);
        float4 bb = *reinterpret_cast<const float4*>(be + i * 128 + lane * 4);
        gv[i * 4 + 0] = gg.x; gv[i * 4 + 1] = gg.y;
        gv[i * 4 + 2] = gg.z; gv[i * 4 + 3] = gg.w;
        bev[i * 4 + 0] = bb.x; bev[i * 4 + 1] = bb.y;
        bev[i * 4 + 2] = bb.z; bev[i * 4 + 3] = bb.w;
    }

    float racc[24];
#pragma unroll
    for (int i = 0; i < 24; i++) racc[i] = 0.0f;

    for (int r = 0; r < 8; r++) {
        const int s = s_base + w * 8 + r;
        const float* __restrict__ row = g_scratch + ((size_t)b * SS + s) * HH;

        float x[24];
        float sum = 0.0f, sq = 0.0f;
#pragma unroll
        for (int i = 0; i < 6; i++) {
            float4 v = *reinterpret_cast<const float4*>(row + i * 128 + lane * 4);
            x[i * 4 + 0] = v.x; x[i * 4 + 1] = v.y;
            x[i * 4 + 2] = v.z; x[i * 4 + 3] = v.w;
            sum += v.x + v.y + v.z + v.w;
            sq += v.x * v.x + v.y * v.y + v.z * v.z + v.w * v.w;
        }
#pragma unroll
        for (int o = 16; o > 0; o >>= 1) {
            sum += __shfl_xor_sync(0xffffffffu, sum, o);
            sq  += __shfl_xor_sync(0xffffffffu, sq, o);
        }
        const float mean = sum * (1.0f / HH);
        const float var = sq * (1.0f / HH) - mean * mean;
        const float rstd = rsqrtf(var + 1e-5f);
        const float mk = mask[b * SS + s];

#pragma unroll
        for (int i = 0; i < 24; i++) {
            float v = (x[i] - mean) * rstd * gv[i] + bev[i];
            racc[i] += fmaxf(v, 0.0f) * mk;
        }
    }

#pragma unroll
    for (int i = 0; i < 6; i++) {
#pragma unroll
        for (int j = 0; j < 4; j++) {
            int c = i * 128 + lane * 4 + j;
            atomicAdd(&accum[c], racc[i * 4 + j]);
        }
    }
    __syncthreads();
    for (int c = tid; c < HH; c += 256)
        atomicAdd(&g_rbar[b * HH + c], accum[c]);
}

// ---------------------------------------------------------------------------
// Kernel 3a: comb[b, n] = (rbar[b] @ W2[l])[n]/D + (M/D)*b2[l,n] for n<HH,
//            comb[b, HH+i] = lda[b,i].
// Grid (HH/256, BB) = (3, 32); 256 threads; thread -> one column (coalesced).
// W2-selected fits in L2 -> L2-throughput bound.
// ---------------------------------------------------------------------------
__global__ __launch_bounds__(256) void gemv2_kernel(
    const int* __restrict__ lang,
    const float* __restrict__ lda,
    const float* __restrict__ W2,
    const float* __restrict__ b2)
{
    const int b = blockIdx.y;
    const int n = blockIdx.x * 256 + threadIdx.x;
    const int tid = threadIdx.x;
    __shared__ float tvec[HH];

    for (int c = tid; c < HH; c += 256) tvec[c] = g_rbar[b * HH + c];
    __syncthreads();

    const int l = lang[b];
    const float Mtot = g_msum[b];
    const float invD = 1.0f / (Mtot + 1e-10f);
    const float* __restrict__ W2l = W2 + (size_t)l * HH * HH;

    float acc = 0.0f;
#pragma unroll 8
    for (int h = 0; h < HH; h++)
        acc += tvec[h] * W2l[(size_t)h * HH + n];

    g_comb[b * (HH + TT) + n] = (acc + Mtot * b2[l * HH + n]) * invD;

    if (blockIdx.x == 0) {
        for (int i = tid; i < TT; i += 256)
            g_comb[b * (HH + TT) + HH + i] = lda[b * TT + i];
    }
}

// ---------------------------------------------------------------------------
// Kernel 3b: g_fused[b, n] = comb[b] @ Wf[:, n] + bf[n]
// Grid (THH/256, BB) = (2, 32); 256 threads; thread -> one column.
// ---------------------------------------------------------------------------
__global__ __launch_bounds__(256) void fuse_kernel(
    const float* __restrict__ Wf,
    const float* __restrict__ bf)
{
    const int b = blockIdx.y;
    const int n = blockIdx.x * 256 + threadIdx.x;
    const int tid = threadIdx.x;
    __shared__ float comb[HH + TT];

    for (int c = tid; c < HH + TT; c += 256) comb[c] = g_comb[b * (HH + TT) + c];
    __syncthreads();

    float f = 0.0f;
#pragma unroll 4
    for (int i = 0; i < HH + TT; i++)
        f += comb[i] * Wf[(size_t)i * THH + n];

    g_fused[b * THH + n] = f + bf[n];
}

// ---------------------------------------------------------------------------
// Kernel 3c: out[b] = relu(LN(g_fused[b]) * gf + bef). Grid BB, block 512.
// ---------------------------------------------------------------------------
__global__ __launch_bounds__(512) void final_ln_kernel(
    const float* __restrict__ gf,
    const float* __restrict__ bef,
    float* __restrict__ out)
{
    const int b = blockIdx.x;
    const int tid = threadIdx.x;
    const int lane = tid & 31;
    const int warp = tid >> 5;
    __shared__ float red[32];

    const float f = g_fused[b * THH + tid];

    float sum = f, sq = f * f;
#pragma unroll
    for (int o = 16; o > 0; o >>= 1) {
        sum += __shfl_xor_sync(0xffffffffu, sum, o);
        sq  += __shfl_xor_sync(0xffffffffu, sq, o);
    }
    if (lane == 0) { red[warp] = sum; red[warp + 16] = sq; }
    __syncthreads();
    if (tid < 32) {
        float v = (tid < 16) ? red[tid] : 0.0f;
        float v2 = (tid < 16) ? red[tid + 16] : 0.0f;
#pragma unroll
        for (int o = 8; o > 0; o >>= 1) {
            v  += __shfl_xor_sync(0xffffffffu, v, o);
            v2 += __shfl_xor_sync(0xffffffffu, v2, o);
        }
        if (tid == 0) { red[0] = v; red[1] = v2; }
    }
    __syncthreads();
    const float mean = red[0] * (1.0f / THH);
    const float var = red[1] * (1.0f / THH) - mean * mean;
    const float rstd = rsqrtf(var + 1e-5f);

    float o = (f - mean) * rstd * gf[tid] + bef[tid];
    out[b * THH + tid] = fmaxf(o, 0.0f);
}

// ---------------------------------------------------------------------------
extern "C" void kernel_launch(void* const* d_in, const int* in_sizes, int n_in,
                              void* d_out, int out_size)
{
    const float* seq  = (const float*)d_in[0];   // [B,S,H]
    const float* mask = (const float*)d_in[1];   // [B,S]
    const int*   lang = (const int*)d_in[2];     // [B]
    const float* lda  = (const float*)d_in[3];   // [B,T]
    const float* W1   = (const float*)d_in[4];   // [L,H,H]
    const float* b1   = (const float*)d_in[5];   // [L,H]
    const float* g1   = (const float*)d_in[6];   // [L,H]
    const float* be1  = (const float*)d_in[7];   // [L,H]
    const float* W2   = (const float*)d_in[8];   // [L,H,H]
    const float* b2   = (const float*)d_in[9];   // [L,H]
    const float* Wf   = (const float*)d_in[10];  // [H+T,TH]
    const float* bf   = (const float*)d_in[11];  // [TH]
    const float* gf   = (const float*)d_in[12];  // [TH]
    const float* bef  = (const float*)d_in[13];  // [TH]
    float* out = (float*)d_out;                  // [B,TH]

    (void)in_sizes; (void)n_in; (void)out_size;

    init_kernel<<<BB, 256>>>(mask);
    gemm1_kernel<<<dim3(HH / 128, (BB * SS) / 128), 256>>>(seq, W1, b1, lang);
    ln_relu_pool_kernel<<<BB * 8, 256>>>(mask, lang, g1, be1);
    gemv2_kernel<<<dim3(HH / 256, BB), 256>>>(lang, lda, W2, b2);
    fuse_kernel<<<dim3(THH / 256, BB), 256>>>(Wf, bf);
    final_ln_kernel<<<BB, 512>>>(gf, bef, out);
}

// round 6
// speedup vs baseline: 2.5563x; 2.0658x over previous
#include <cuda_runtime.h>
#include <cuda_bf16.h>
#include <cstdint>

// Problem constants
#define BB 32
#define SS 512
#define HH 768
#define TT 100
#define THH 512
#define LL 5

// Scratch (static device globals — no allocation)
__device__ float g_scratch[BB * SS * HH];   // GEMM1 output: 50.3 MB
__device__ float g_rbar[BB * HH];
__device__ float g_msum[BB];
__device__ float g_comb[BB * (HH + TT)];
__device__ float g_fused[BB * THH];
__device__ __align__(16) __nv_bfloat16 g_w1t_hi[LL * HH * HH];  // W1^T hi, [L][N][K]
__device__ __align__(16) __nv_bfloat16 g_w1t_lo[LL * HH * HH];  // W1^T lo

// ---------------------------------------------------------------------------
// mma.sync m16n8k16 bf16 (legacy HMMA path — supported on base sm_100)
// ---------------------------------------------------------------------------
__device__ __forceinline__ void mma_bf16(float* c, const uint32_t* a, const uint32_t* b) {
    asm volatile(
        "mma.sync.aligned.m16n8k16.row.col.f32.bf16.bf16.f32 "
        "{%0,%1,%2,%3}, {%4,%5,%6,%7}, {%8,%9}, {%0,%1,%2,%3};"
        : "+f"(c[0]), "+f"(c[1]), "+f"(c[2]), "+f"(c[3])
        : "r"(a[0]), "r"(a[1]), "r"(a[2]), "r"(a[3]), "r"(b[0]), "r"(b[1]));
}

// ===========================================================================
// Kernel: init — zero rbar, mask sums, seed comb (bias+lda) and fused (bf)
// ===========================================================================
__global__ __launch_bounds__(256) void init_kernel(
    const float* __restrict__ mask, const int* __restrict__ lang,
    const float* __restrict__ b2, const float* __restrict__ lda,
    const float* __restrict__ bf)
{
    const int b = blockIdx.x;
    const int tid = threadIdx.x;
    const int lane = tid & 31;
    const int warp = tid >> 5;
    __shared__ float red[8];
    __shared__ float sh_m;

    for (int c = tid; c < HH; c += 256) g_rbar[b * HH + c] = 0.0f;

    float ms = 0.0f;
    for (int s = tid; s < SS; s += 256) ms += mask[b * SS + s];
#pragma unroll
    for (int o = 16; o > 0; o >>= 1) ms += __shfl_xor_sync(0xffffffffu, ms, o);
    if (lane == 0) red[warp] = ms;
    __syncthreads();
    if (tid == 0) {
        float v = 0.0f;
#pragma unroll
        for (int i = 0; i < 8; i++) v += red[i];
        g_msum[b] = v;
        sh_m = v;
    }
    __syncthreads();

    const int l = lang[b];
    const float Mtot = sh_m;
    const float invD = 1.0f / (Mtot + 1e-10f);
    for (int n = tid; n < HH; n += 256)
        g_comb[b * (HH + TT) + n] = Mtot * b2[l * HH + n] * invD;
    for (int i = tid; i < TT; i += 256)
        g_comb[b * (HH + TT) + HH + i] = lda[b * TT + i];
    for (int n = tid; n < THH; n += 256)
        g_fused[b * THH + n] = bf[n];
}

// ===========================================================================
// Kernel: W1 -> W1^T split to bf16 hi/lo. grid (24,24,L), block (32,8)
// Output layout [L][N][K] = col-major B, exactly what mma.row.col wants.
// ===========================================================================
__global__ __launch_bounds__(256) void w1t_prep_kernel(const float* __restrict__ W1)
{
    __shared__ float tile[32][33];
    const int l = blockIdx.z;
    const int n0 = blockIdx.x * 32;
    const int k0 = blockIdx.y * 32;
    const float* __restrict__ W = W1 + (size_t)l * HH * HH;
#pragma unroll
    for (int j = 0; j < 4; j++) {
        int k = k0 + threadIdx.y + j * 8;
        tile[threadIdx.y + j * 8][threadIdx.x] = W[(size_t)k * HH + n0 + threadIdx.x];
    }
    __syncthreads();
#pragma unroll
    for (int j = 0; j < 4; j++) {
        int n = n0 + threadIdx.y + j * 8;
        float v = tile[threadIdx.x][threadIdx.y + j * 8];
        __nv_bfloat16 h = __float2bfloat16(v);
        __nv_bfloat16 lo = __float2bfloat16(v - __bfloat162float(h));
        size_t o = (size_t)l * HH * HH + (size_t)n * HH + k0 + threadIdx.x;
        g_w1t_hi[o] = h;
        g_w1t_lo[o] = lo;
    }
}

// ===========================================================================
// Kernel: GEMM1 via mma.sync bf16-split.
// CTA tile 128x128, BK=32, 8 warps (2m x 4n), warp tile 64x32.
// grid (6, 128), 256 threads, 40KB static smem, reg-prefetch pipeline.
// ===========================================================================
#define BKP 40   // padded K stride (bf16 elems): 32 + 8

__global__ __launch_bounds__(256) void gemm1_mma_kernel(
    const float* __restrict__ seq,
    const int* __restrict__ lang,
    const float* __restrict__ b1)
{
    __shared__ __nv_bfloat16 As_hi[128][BKP];
    __shared__ __nv_bfloat16 As_lo[128][BKP];
    __shared__ __nv_bfloat16 Bs_hi[128][BKP];
    __shared__ __nv_bfloat16 Bs_lo[128][BKP];

    const int tid = threadIdx.x;
    const int wid = tid >> 5;
    const int lane = tid & 31;
    const int g = lane >> 2;      // groupID 0..7
    const int tg = lane & 3;      // thread-in-group

    const int n0 = blockIdx.x * 128;
    const int m0 = blockIdx.y * 128;
    const int b = m0 / SS;
    const int l = lang[b];

    const int wm = (wid & 1) * 64;   // warp m offset
    const int wn = (wid >> 1) * 32;  // warp n offset

    const __nv_bfloat16* __restrict__ WhT = g_w1t_hi + (size_t)l * HH * HH;
    const __nv_bfloat16* __restrict__ WlT = g_w1t_lo + (size_t)l * HH * HH;

    // A load coords: 1024 float4 per chunk (4/thread). 8 float4 per row.
    const int a_row = (tid * 4) >> 3;        // rows: 4 consecutive f4 -> same... no:
    // use idx = tid + 256*i below instead.
    (void)a_row;

    float acc[4][4][4];
#pragma unroll
    for (int mi = 0; mi < 4; mi++)
#pragma unroll
        for (int ni = 0; ni < 4; ni++)
#pragma unroll
            for (int r = 0; r < 4; r++) acc[mi][ni][r] = 0.0f;

    // ---- prologue prefetch (chunk 0) ----
    float4 ra[4];
    uint4 rbh[2], rbl[2];
#pragma unroll
    for (int i = 0; i < 4; i++) {
        int idx = tid + 256 * i;          // 0..1023
        int row = idx >> 3;               // 8 float4 per 32-float row
        int c4 = (idx & 7) * 4;
        ra[i] = *reinterpret_cast<const float4*>(seq + (size_t)(m0 + row) * HH + c4);
    }
#pragma unroll
    for (int i = 0; i < 2; i++) {
        int idx = tid + 256 * i;          // 0..511
        int row = idx >> 2;               // 4 uint4 per 32-bf16 row
        int c8 = (idx & 3) * 8;
        rbh[i] = *reinterpret_cast<const uint4*>(WhT + (size_t)(n0 + row) * HH + c8);
        rbl[i] = *reinterpret_cast<const uint4*>(WlT + (size_t)(n0 + row) * HH + c8);
    }

    for (int it = 0; it < HH / 32; ++it) {
        // ---- commit staged regs to smem (A split to hi/lo) ----
#pragma unroll
        for (int i = 0; i < 4; i++) {
            int idx = tid + 256 * i;
            int row = idx >> 3;
            int c4 = (idx & 7) * 4;
            const float* xf = reinterpret_cast<const float*>(&ra[i]);
            uint32_t h[2], lo[2];
#pragma unroll
            for (int j = 0; j < 2; j++) {
                float v0 = xf[2 * j], v1 = xf[2 * j + 1];
                __nv_bfloat16 h0 = __float2bfloat16(v0);
                __nv_bfloat16 h1 = __float2bfloat16(v1);
                __nv_bfloat16 l0 = __float2bfloat16(v0 - __bfloat162float(h0));
                __nv_bfloat16 l1 = __float2bfloat16(v1 - __bfloat162float(h1));
                h[j]  = ((uint32_t)__bfloat16_as_ushort(h1) << 16) | __bfloat16_as_ushort(h0);
                lo[j] = ((uint32_t)__bfloat16_as_ushort(l1) << 16) | __bfloat16_as_ushort(l0);
            }
            *reinterpret_cast<uint2*>(&As_hi[row][c4]) = make_uint2(h[0], h[1]);
            *reinterpret_cast<uint2*>(&As_lo[row][c4]) = make_uint2(lo[0], lo[1]);
        }
#pragma unroll
        for (int i = 0; i < 2; i++) {
            int idx = tid + 256 * i;
            int row = idx >> 2;
            int c8 = (idx & 3) * 8;
            *reinterpret_cast<uint4*>(&Bs_hi[row][c8]) = rbh[i];
            *reinterpret_cast<uint4*>(&Bs_lo[row][c8]) = rbl[i];
        }
        __syncthreads();

        // ---- prefetch next chunk ----
        if (it + 1 < HH / 32) {
            const int k0 = (it + 1) * 32;
#pragma unroll
            for (int i = 0; i < 4; i++) {
                int idx = tid + 256 * i;
                int row = idx >> 3;
                int c4 = (idx & 7) * 4;
                ra[i] = *reinterpret_cast<const float4*>(
                    seq + (size_t)(m0 + row) * HH + k0 + c4);
            }
#pragma unroll
            for (int i = 0; i < 2; i++) {
                int idx = tid + 256 * i;
                int row = idx >> 2;
                int c8 = (idx & 3) * 8;
                rbh[i] = *reinterpret_cast<const uint4*>(
                    WhT + (size_t)(n0 + row) * HH + k0 + c8);
                rbl[i] = *reinterpret_cast<const uint4*>(
                    WlT + (size_t)(n0 + row) * HH + k0 + c8);
            }
        }

        // ---- compute: 2 k16 steps ----
#pragma unroll
        for (int ks = 0; ks < 2; ks++) {
            const int kk = ks * 16;
            // B fragments for 4 n-tiles (hi & lo)
            uint32_t bh[4][2], blo[4][2];
#pragma unroll
            for (int ni = 0; ni < 4; ni++) {
                int n = wn + ni * 8 + g;
                bh[ni][0]  = *reinterpret_cast<const uint32_t*>(&Bs_hi[n][kk + tg * 2]);
                bh[ni][1]  = *reinterpret_cast<const uint32_t*>(&Bs_hi[n][kk + 8 + tg * 2]);
                blo[ni][0] = *reinterpret_cast<const uint32_t*>(&Bs_lo[n][kk + tg * 2]);
                blo[ni][1] = *reinterpret_cast<const uint32_t*>(&Bs_lo[n][kk + 8 + tg * 2]);
            }
#pragma unroll
            for (int mi = 0; mi < 4; mi++) {
                int m = wm + mi * 16 + g;
                uint32_t ah[4], al[4];
                ah[0] = *reinterpret_cast<const uint32_t*>(&As_hi[m][kk + tg * 2]);
                ah[1] = *reinterpret_cast<const uint32_t*>(&As_hi[m + 8][kk + tg * 2]);
                ah[2] = *reinterpret_cast<const uint32_t*>(&As_hi[m][kk + 8 + tg * 2]);
                ah[3] = *reinterpret_cast<const uint32_t*>(&As_hi[m + 8][kk + 8 + tg * 2]);
                al[0] = *reinterpret_cast<const uint32_t*>(&As_lo[m][kk + tg * 2]);
                al[1] = *reinterpret_cast<const uint32_t*>(&As_lo[m + 8][kk + tg * 2]);
                al[2] = *reinterpret_cast<const uint32_t*>(&As_lo[m][kk + 8 + tg * 2]);
                al[3] = *reinterpret_cast<const uint32_t*>(&As_lo[m + 8][kk + 8 + tg * 2]);
#pragma unroll
                for (int ni = 0; ni < 4; ni++) {
                    mma_bf16(acc[mi][ni], ah, bh[ni]);
                    mma_bf16(acc[mi][ni], ah, blo[ni]);
                    mma_bf16(acc[mi][ni], al, bh[ni]);
                }
            }
        }
        __syncthreads();
    }

    // ---- epilogue: add bias, write to g_scratch ----
    const float* __restrict__ bp = b1 + (size_t)l * HH;
#pragma unroll
    for (int ni = 0; ni < 4; ni++) {
        int n = n0 + wn + ni * 8 + tg * 2;
        float2 bv = *reinterpret_cast<const float2*>(bp + n);
#pragma unroll
        for (int mi = 0; mi < 4; mi++) {
            int mA = m0 + wm + mi * 16 + g;
            float2 o0, o1;
            o0.x = acc[mi][ni][0] + bv.x;
            o0.y = acc[mi][ni][1] + bv.y;
            o1.x = acc[mi][ni][2] + bv.x;
            o1.y = acc[mi][ni][3] + bv.y;
            *reinterpret_cast<float2*>(g_scratch + (size_t)mA * HH + n) = o0;
            *reinterpret_cast<float2*>(g_scratch + (size_t)(mA + 8) * HH + n) = o1;
        }
    }
}

// ===========================================================================
// Kernel: LN + ReLU + masked pool
// ===========================================================================
__global__ __launch_bounds__(256) void ln_relu_pool_kernel(
    const float* __restrict__ mask,
    const int* __restrict__ lang,
    const float* __restrict__ g1,
    const float* __restrict__ be1)
{
    __shared__ float accum[HH];
    const int blk = blockIdx.x;
    const int b = blk >> 3;
    const int s_base = (blk & 7) * 64;
    const int tid = threadIdx.x;
    const int w = tid >> 5;
    const int lane = tid & 31;

    for (int c = tid; c < HH; c += 256) accum[c] = 0.0f;
    __syncthreads();

    const int l = lang[b];
    const float* __restrict__ g = g1 + (size_t)l * HH;
    const float* __restrict__ be = be1 + (size_t)l * HH;

    float gv[24], bev[24];
#pragma unroll
    for (int i = 0; i < 6; i++) {
        float4 gg = *reinterpret_cast<const float4*>(g + i * 128 + lane * 4);
        float4 bb = *reinterpret_cast<const float4*>(be + i * 128 + lane * 4);
        gv[i * 4 + 0] = gg.x; gv[i * 4 + 1] = gg.y;
        gv[i * 4 + 2] = gg.z; gv[i * 4 + 3] = gg.w;
        bev[i * 4 + 0] = bb.x; bev[i * 4 + 1] = bb.y;
        bev[i * 4 + 2] = bb.z; bev[i * 4 + 3] = bb.w;
    }

    float racc[24];
#pragma unroll
    for (int i = 0; i < 24; i++) racc[i] = 0.0f;

    for (int r = 0; r < 8; r++) {
        const int s = s_base + w * 8 + r;
        const float* __restrict__ row = g_scratch + ((size_t)b * SS + s) * HH;

        float x[24];
        float sum = 0.0f, sq = 0.0f;
#pragma unroll
        for (int i = 0; i < 6; i++) {
            float4 v = *reinterpret_cast<const float4*>(row + i * 128 + lane * 4);
            x[i * 4 + 0] = v.x; x[i * 4 + 1] = v.y;
            x[i * 4 + 2] = v.z; x[i * 4 + 3] = v.w;
            sum += v.x + v.y + v.z + v.w;
            sq += v.x * v.x + v.y * v.y + v.z * v.z + v.w * v.w;
        }
#pragma unroll
        for (int o = 16; o > 0; o >>= 1) {
            sum += __shfl_xor_sync(0xffffffffu, sum, o);
            sq  += __shfl_xor_sync(0xffffffffu, sq, o);
        }
        const float mean = sum * (1.0f / HH);
        const float var = sq * (1.0f / HH) - mean * mean;
        const float rstd = rsqrtf(var + 1e-5f);
        const float mk = mask[b * SS + s];

#pragma unroll
        for (int i = 0; i < 24; i++) {
            float v = (x[i] - mean) * rstd * gv[i] + bev[i];
            racc[i] += fmaxf(v, 0.0f) * mk;
        }
    }

#pragma unroll
    for (int i = 0; i < 6; i++) {
#pragma unroll
        for (int j = 0; j < 4; j++) {
            int c = i * 128 + lane * 4 + j;
            atomicAdd(&accum[c], racc[i * 4 + j]);
        }
    }
    __syncthreads();
    for (int c = tid; c < HH; c += 256)
        atomicAdd(&g_rbar[b * HH + c], accum[c]);
}

// ===========================================================================
// Kernel: gemv2 split-K. grid (3, BB, 4). Partial dot into g_comb (atomic).
// ===========================================================================
__global__ __launch_bounds__(256) void gemv2_kernel(
    const int* __restrict__ lang,
    const float* __restrict__ W2)
{
    const int b = blockIdx.y;
    const int z = blockIdx.z;
    const int n = blockIdx.x * 256 + threadIdx.x;
    const int tid = threadIdx.x;
    const int kb = z * 192;
    __shared__ float tvec[192];

    if (tid < 192) tvec[tid] = g_rbar[b * HH + kb + tid];
    __syncthreads();

    const int l = lang[b];
    const float invD = 1.0f / (g_msum[b] + 1e-10f);
    const float* __restrict__ W2l = W2 + (size_t)l * HH * HH + (size_t)kb * HH;

    float acc = 0.0f;
#pragma unroll 8
    for (int h = 0; h < 192; h++)
        acc += tvec[h] * W2l[(size_t)h * HH + n];

    atomicAdd(&g_comb[b * (HH + TT) + n], acc * invD);
}

// ===========================================================================
// Kernel: fuse split-K. grid (2, BB, 4). 868 = 4*217.
// ===========================================================================
__global__ __launch_bounds__(256) void fuse_kernel(const float* __restrict__ Wf)
{
    const int b = blockIdx.y;
    const int z = blockIdx.z;
    const int n = blockIdx.x * 256 + threadIdx.x;
    const int tid = threadIdx.x;
    const int ib = z * 217;
    __shared__ float comb[217];

    if (tid < 217) comb[tid] = g_comb[b * (HH + TT) + ib + tid];
    __syncthreads();

    float f = 0.0f;
#pragma unroll 7
    for (int i = 0; i < 217; i++)
        f += comb[i] * Wf[(size_t)(ib + i) * THH + n];

    atomicAdd(&g_fused[b * THH + n], f);
}

// ===========================================================================
// Kernel: final LN + relu. grid BB, block 512.
// ===========================================================================
__global__ __launch_bounds__(512) void final_ln_kernel(
    const float* __restrict__ gf,
    const float* __restrict__ bef,
    float* __restrict__ out)
{
    const int b = blockIdx.x;
    const int tid = threadIdx.x;
    const int lane = tid & 31;
    const int warp = tid >> 5;
    __shared__ float red[32];

    const float f = g_fused[b * THH + tid];

    float sum = f, sq = f * f;
#pragma unroll
    for (int o = 16; o > 0; o >>= 1) {
        sum += __shfl_xor_sync(0xffffffffu, sum, o);
        sq  += __shfl_xor_sync(0xffffffffu, sq, o);
    }
    if (lane == 0) { red[warp] = sum; red[warp + 16] = sq; }
    __syncthreads();
    if (tid < 32) {
        float v = (tid < 16) ? red[tid] : 0.0f;
        float v2 = (tid < 16) ? red[tid + 16] : 0.0f;
#pragma unroll
        for (int o = 8; o > 0; o >>= 1) {
            v  += __shfl_xor_sync(0xffffffffu, v, o);
            v2 += __shfl_xor_sync(0xffffffffu, v2, o);
        }
        if (tid == 0) { red[0] = v; red[1] = v2; }
    }
    __syncthreads();
    const float mean = red[0] * (1.0f / THH);
    const float var = red[1] * (1.0f / THH) - mean * mean;
    const float rstd = rsqrtf(var + 1e-5f);

    float o = (f - mean) * rstd * gf[tid] + bef[tid];
    out[b * THH + tid] = fmaxf(o, 0.0f);
}

// ===========================================================================
extern "C" void kernel_launch(void* const* d_in, const int* in_sizes, int n_in,
                              void* d_out, int out_size)
{
    const float* seq  = (const float*)d_in[0];
    const float* mask = (const float*)d_in[1];
    const int*   lang = (const int*)d_in[2];
    const float* lda  = (const float*)d_in[3];
    const float* W1   = (const float*)d_in[4];
    const float* b1   = (const float*)d_in[5];
    const float* g1   = (const float*)d_in[6];
    const float* be1  = (const float*)d_in[7];
    const float* W2   = (const float*)d_in[8];
    const float* b2   = (const float*)d_in[9];
    const float* Wf   = (const float*)d_in[10];
    const float* bf   = (const float*)d_in[11];
    const float* gf   = (const float*)d_in[12];
    const float* bef  = (const float*)d_in[13];
    float* out = (float*)d_out;

    (void)in_sizes; (void)n_in; (void)out_size;

    init_kernel<<<BB, 256>>>(mask, lang, b2, lda, bf);
    w1t_prep_kernel<<<dim3(HH / 32, HH / 32, LL), dim3(32, 8)>>>(W1);
    gemm1_mma_kernel<<<dim3(HH / 128, (BB * SS) / 128), 256>>>(seq, lang, b1);
    ln_relu_pool_kernel<<<BB * 8, 256>>>(mask, lang, g1, be1);
    gemv2_kernel<<<dim3(3, BB, 4), 256>>>(lang, W2);
    fuse_kernel<<<dim3(2, BB, 4), 256>>>(Wf);
    final_ln_kernel<<<BB, 512>>>(gf, bef, out);
}

// round 8
// speedup vs baseline: 2.7679x; 1.0828x over previous
#include <cuda_runtime.h>
#include <cuda_bf16.h>
#include <cstdint>

// Problem constants
#define BB 32
#define SS 512
#define HH 768
#define TT 100
#define THH 512
#define LL 5

// Scratch (static device globals — no allocation)
__device__ float g_scratch[BB * SS * HH];   // GEMM1 output: 50.3 MB
__device__ float g_rbar[BB * HH];
__device__ float g_msum[BB];
__device__ float g_comb[BB * (HH + TT)];
__device__ float g_fused[BB * THH];
__device__ __align__(16) __nv_bfloat16 g_w1t_hi[LL * HH * HH];  // W1^T hi, [L][N][K]
__device__ __align__(16) __nv_bfloat16 g_w1t_lo[LL * HH * HH];  // W1^T lo

// ---------------------------------------------------------------------------
// mma.sync m16n8k16 bf16 + ldmatrix (legacy paths, supported on base sm_100)
// ---------------------------------------------------------------------------
__device__ __forceinline__ void mma_bf16(float* c, const uint32_t* a, const uint32_t* b) {
    asm volatile(
        "mma.sync.aligned.m16n8k16.row.col.f32.bf16.bf16.f32 "
        "{%0,%1,%2,%3}, {%4,%5,%6,%7}, {%8,%9}, {%0,%1,%2,%3};"
        : "+f"(c[0]), "+f"(c[1]), "+f"(c[2]), "+f"(c[3])
        : "r"(a[0]), "r"(a[1]), "r"(a[2]), "r"(a[3]), "r"(b[0]), "r"(b[1]));
}
__device__ __forceinline__ void ldsm_x4(uint32_t* r, uint32_t saddr) {
    asm volatile(
        "ldmatrix.sync.aligned.m8n8.x4.shared.b16 {%0,%1,%2,%3}, [%4];"
        : "=r"(r[0]), "=r"(r[1]), "=r"(r[2]), "=r"(r[3]) : "r"(saddr));
}
__device__ __forceinline__ uint32_t smem_u32(const void* p) {
    uint32_t a;
    asm("{ .reg .u64 t; cvta.to.shared.u64 t, %1; cvt.u32.u64 %0, t; }"
        : "=r"(a) : "l"(p));
    return a;
}

// ===========================================================================
// Kernel: init — zero rbar, mask sums, seed comb (bias+lda) and fused (bf)
// ===========================================================================
__global__ __launch_bounds__(256) void init_kernel(
    const float* __restrict__ mask, const int* __restrict__ lang,
    const float* __restrict__ b2, const float* __restrict__ lda,
    const float* __restrict__ bf)
{
    const int b = blockIdx.x;
    const int tid = threadIdx.x;
    const int lane = tid & 31;
    const int warp = tid >> 5;
    __shared__ float red[8];
    __shared__ float sh_m;

    for (int c = tid; c < HH; c += 256) g_rbar[b * HH + c] = 0.0f;

    float ms = 0.0f;
    for (int s = tid; s < SS; s += 256) ms += mask[b * SS + s];
#pragma unroll
    for (int o = 16; o > 0; o >>= 1) ms += __shfl_xor_sync(0xffffffffu, ms, o);
    if (lane == 0) red[warp] = ms;
    __syncthreads();
    if (tid == 0) {
        float v = 0.0f;
#pragma unroll
        for (int i = 0; i < 8; i++) v += red[i];
        g_msum[b] = v;
        sh_m = v;
    }
    __syncthreads();

    const int l = lang[b];
    const float Mtot = sh_m;
    const float invD = 1.0f / (Mtot + 1e-10f);
    for (int n = tid; n < HH; n += 256)
        g_comb[b * (HH + TT) + n] = Mtot * b2[l * HH + n] * invD;
    for (int i = tid; i < TT; i += 256)
        g_comb[b * (HH + TT) + HH + i] = lda[b * TT + i];
    for (int n = tid; n < THH; n += 256)
        g_fused[b * THH + n] = bf[n];
}

// ===========================================================================
// Kernel: W1 -> W1^T split to bf16 hi/lo. grid (24,24,L), block (32,8)
// ===========================================================================
__global__ __launch_bounds__(256) void w1t_prep_kernel(const float* __restrict__ W1)
{
    __shared__ float tile[32][33];
    const int l = blockIdx.z;
    const int n0 = blockIdx.x * 32;
    const int k0 = blockIdx.y * 32;
    const float* __restrict__ W = W1 + (size_t)l * HH * HH;
#pragma unroll
    for (int j = 0; j < 4; j++) {
        int k = k0 + threadIdx.y + j * 8;
        tile[threadIdx.y + j * 8][threadIdx.x] = W[(size_t)k * HH + n0 + threadIdx.x];
    }
    __syncthreads();
#pragma unroll
    for (int j = 0; j < 4; j++) {
        int n = n0 + threadIdx.y + j * 8;
        float v = tile[threadIdx.x][threadIdx.y + j * 8];
        __nv_bfloat16 h = __float2bfloat16(v);
        __nv_bfloat16 lo = __float2bfloat16(v - __bfloat162float(h));
        size_t o = (size_t)l * HH * HH + (size_t)n * HH + k0 + threadIdx.x;
        g_w1t_hi[o] = h;
        g_w1t_lo[o] = lo;
    }
}

// ===========================================================================
// Kernel: GEMM1 via mma.sync bf16-split + ldmatrix.
// CTA tile 128x128, BK=32, 8 warps (2m x 4n), warp tile 64x32.
// ===========================================================================
#define BKP 40   // padded K stride (bf16 elems): 32 + 8 -> 80B rows, LDSM-conflict-free

__global__ __launch_bounds__(256) void gemm1_mma_kernel(
    const float* __restrict__ seq,
    const int* __restrict__ lang,
    const float* __restrict__ b1)
{
    __shared__ __nv_bfloat16 As_hi[128][BKP];
    __shared__ __nv_bfloat16 As_lo[128][BKP];
    __shared__ __nv_bfloat16 Bs_hi[128][BKP];
    __shared__ __nv_bfloat16 Bs_lo[128][BKP];

    const int tid = threadIdx.x;
    const int wid = tid >> 5;
    const int lane = tid & 31;
    const int g = lane >> 2;
    const int tg = lane & 3;

    const int n0 = blockIdx.x * 128;
    const int m0 = blockIdx.y * 128;
    const int b = m0 / SS;
    const int l = lang[b];

    const int wm = (wid & 1) * 64;   // warp m offset
    const int wn = (wid >> 1) * 32;  // warp n offset

    // ldmatrix per-lane source coords
    const int a_r = (lane & 7) + 8 * ((lane >> 3) & 1);  // row-in-16 (m)
    const int a_c = 8 * (lane >> 4);                     // col-in-16 (k)
    const int b_r = (lane & 7) + 8 * (lane >> 4);        // row-in-16 (n)
    const int b_c = 8 * ((lane >> 3) & 1);               // col-in-16 (k)

    const uint32_t as_hi = smem_u32(As_hi);
    const uint32_t as_lo = smem_u32(As_lo);
    const uint32_t bs_hi = smem_u32(Bs_hi);
    const uint32_t bs_lo = smem_u32(Bs_lo);

    const __nv_bfloat16* __restrict__ WhT = g_w1t_hi + (size_t)l * HH * HH;
    const __nv_bfloat16* __restrict__ WlT = g_w1t_lo + (size_t)l * HH * HH;

    float acc[4][4][4];
#pragma unroll
    for (int mi = 0; mi < 4; mi++)
#pragma unroll
        for (int ni = 0; ni < 4; ni++)
#pragma unroll
            for (int r = 0; r < 4; r++) acc[mi][ni][r] = 0.0f;

    // ---- prologue prefetch (chunk 0) ----
    float4 ra[4];
    uint4 rbh[2], rbl[2];
#pragma unroll
    for (int i = 0; i < 4; i++) {
        int idx = tid + 256 * i;
        int row = idx >> 3;
        int c4 = (idx & 7) * 4;
        ra[i] = *reinterpret_cast<const float4*>(seq + (size_t)(m0 + row) * HH + c4);
    }
#pragma unroll
    for (int i = 0; i < 2; i++) {
        int idx = tid + 256 * i;
        int row = idx >> 2;
        int c8 = (idx & 3) * 8;
        rbh[i] = *reinterpret_cast<const uint4*>(WhT + (size_t)(n0 + row) * HH + c8);
        rbl[i] = *reinterpret_cast<const uint4*>(WlT + (size_t)(n0 + row) * HH + c8);
    }

    for (int it = 0; it < HH / 32; ++it) {
        // ---- commit staged regs to smem (A split to hi/lo) ----
#pragma unroll
        for (int i = 0; i < 4; i++) {
            int idx = tid + 256 * i;
            int row = idx >> 3;
            int c4 = (idx & 7) * 4;
            const float* xf = reinterpret_cast<const float*>(&ra[i]);
            uint32_t h[2], lo[2];
#pragma unroll
            for (int j = 0; j < 2; j++) {
                float v0 = xf[2 * j], v1 = xf[2 * j + 1];
                __nv_bfloat16 h0 = __float2bfloat16(v0);
                __nv_bfloat16 h1 = __float2bfloat16(v1);
                __nv_bfloat16 l0 = __float2bfloat16(v0 - __bfloat162float(h0));
                __nv_bfloat16 l1 = __float2bfloat16(v1 - __bfloat162float(h1));
                h[j]  = ((uint32_t)__bfloat16_as_ushort(h1) << 16) | __bfloat16_as_ushort(h0);
                lo[j] = ((uint32_t)__bfloat16_as_ushort(l1) << 16) | __bfloat16_as_ushort(l0);
            }
            *reinterpret_cast<uint2*>(&As_hi[row][c4]) = make_uint2(h[0], h[1]);
            *reinterpret_cast<uint2*>(&As_lo[row][c4]) = make_uint2(lo[0], lo[1]);
        }
#pragma unroll
        for (int i = 0; i < 2; i++) {
            int idx = tid + 256 * i;
            int row = idx >> 2;
            int c8 = (idx & 3) * 8;
            *reinterpret_cast<uint4*>(&Bs_hi[row][c8]) = rbh[i];
            *reinterpret_cast<uint4*>(&Bs_lo[row][c8]) = rbl[i];
        }
        __syncthreads();

        // ---- prefetch next chunk ----
        if (it + 1 < HH / 32) {
            const int k0 = (it + 1) * 32;
#pragma unroll
            for (int i = 0; i < 4; i++) {
                int idx = tid + 256 * i;
                int row = idx >> 3;
                int c4 = (idx & 7) * 4;
                ra[i] = *reinterpret_cast<const float4*>(
                    seq + (size_t)(m0 + row) * HH + k0 + c4);
            }
#pragma unroll
            for (int i = 0; i < 2; i++) {
                int idx = tid + 256 * i;
                int row = idx >> 2;
                int c8 = (idx & 3) * 8;
                rbh[i] = *reinterpret_cast<const uint4*>(
                    WhT + (size_t)(n0 + row) * HH + k0 + c8);
                rbl[i] = *reinterpret_cast<const uint4*>(
                    WlT + (size_t)(n0 + row) * HH + k0 + c8);
            }
        }

        // ---- compute: 2 k16 steps, ldmatrix-fed ----
#pragma unroll
        for (int ks = 0; ks < 2; ks++) {
            const int kk = ks * 16;

            // B fragments: 2 ldmatrix.x4 per precision (covers all 4 ni)
            uint32_t bh[2][4], bl[2][4];
#pragma unroll
            for (int p = 0; p < 2; p++) {
                uint32_t off = (uint32_t)((wn + p * 16 + b_r) * BKP + kk + b_c) * 2;
                ldsm_x4(bh[p], bs_hi + off);
                ldsm_x4(bl[p], bs_lo + off);
            }

            // A hi fragments for all mi
            uint32_t ah[4][4];
#pragma unroll
            for (int mi = 0; mi < 4; mi++) {
                uint32_t off = (uint32_t)((wm + mi * 16 + a_r) * BKP + kk + a_c) * 2;
                ldsm_x4(ah[mi], as_hi + off);
            }
            // hi*hi and hi*lo
#pragma unroll
            for (int mi = 0; mi < 4; mi++) {
#pragma unroll
                for (int ni = 0; ni < 4; ni++) {
                    mma_bf16(acc[mi][ni], ah[mi], &bh[ni >> 1][(ni & 1) * 2]);
                    mma_bf16(acc[mi][ni], ah[mi], &bl[ni >> 1][(ni & 1) * 2]);
                }
            }
            // lo*hi
#pragma unroll
            for (int mi = 0; mi < 4; mi++) {
                uint32_t al[4];
                uint32_t off = (uint32_t)((wm + mi * 16 + a_r) * BKP + kk + a_c) * 2;
                ldsm_x4(al, as_lo + off);
#pragma unroll
                for (int ni = 0; ni < 4; ni++)
                    mma_bf16(acc[mi][ni], al, &bh[ni >> 1][(ni & 1) * 2]);
            }
        }
        __syncthreads();
    }

    // ---- epilogue: add bias, write to g_scratch ----
    const float* __restrict__ bp = b1 + (size_t)l * HH;
#pragma unroll
    for (int ni = 0; ni < 4; ni++) {
        int n = n0 + wn + ni * 8 + tg * 2;
        float2 bv = *reinterpret_cast<const float2*>(bp + n);
#pragma unroll
        for (int mi = 0; mi < 4; mi++) {
            int mA = m0 + wm + mi * 16 + g;
            float2 o0, o1;
            o0.x = acc[mi][ni][0] + bv.x;
            o0.y = acc[mi][ni][1] + bv.y;
            o1.x = acc[mi][ni][2] + bv.x;
            o1.y = acc[mi][ni][3] + bv.y;
            *reinterpret_cast<float2*>(g_scratch + (size_t)mA * HH + n) = o0;
            *reinterpret_cast<float2*>(g_scratch + (size_t)(mA + 8) * HH + n) = o1;
        }
    }
}

// ===========================================================================
// Kernel: LN + ReLU + masked pool
// ===========================================================================
__global__ __launch_bounds__(256) void ln_relu_pool_kernel(
    const float* __restrict__ mask,
    const int* __restrict__ lang,
    const float* __restrict__ g1,
    const float* __restrict__ be1)
{
    __shared__ float accum[HH];
    const int blk = blockIdx.x;
    const int b = blk >> 3;
    const int s_base = (blk & 7) * 64;
    const int tid = threadIdx.x;
    const int w = tid >> 5;
    const int lane = tid & 31;

    for (int c = tid; c < HH; c += 256) accum[c] = 0.0f;
    __syncthreads();

    const int l = lang[b];
    const float* __restrict__ g = g1 + (size_t)l * HH;
    const float* __restrict__ be = be1 + (size_t)l * HH;

    float gv[24], bev[24];
#pragma unroll
    for (int i = 0; i < 6; i++) {
        float4 gg = *reinterpret_cast<const float4*>(g + i * 128 + lane * 4);
        float4 bb = *reinterpret_cast<const float4*>(be + i * 128 + lane * 4);
        gv[i * 4 + 0] = gg.x; gv[i * 4 + 1] = gg.y;
        gv[i * 4 + 2] = gg.z; gv[i * 4 + 3] = gg.w;
        bev[i * 4 + 0] = bb.x; bev[i * 4 + 1] = bb.y;
        bev[i * 4 + 2] = bb.z; bev[i * 4 + 3] = bb.w;
    }

    float racc[24];
#pragma unroll
    for (int i = 0; i < 24; i++) racc[i] = 0.0f;

    for (int r = 0; r < 8; r++) {
        const int s = s_base + w * 8 + r;
        const float* __restrict__ row = g_scratch + ((size_t)b * SS + s) * HH;

        float x[24];
        float sum = 0.0f, sq = 0.0f;
#pragma unroll
        for (int i = 0; i < 6; i++) {
            float4 v = *reinterpret_cast<const float4*>(row + i * 128 + lane * 4);
            x[i * 4 + 0] = v.x; x[i * 4 + 1] = v.y;
            x[i * 4 + 2] = v.z; x[i * 4 + 3] = v.w;
            sum += v.x + v.y + v.z + v.w;
            sq += v.x * v.x + v.y * v.y + v.z * v.z + v.w * v.w;
        }
#pragma unroll
        for (int o = 16; o > 0; o >>= 1) {
            sum += __shfl_xor_sync(0xffffffffu, sum, o);
            sq  += __shfl_xor_sync(0xffffffffu, sq, o);
        }
        const float mean = sum * (1.0f / HH);
        const float var = sq * (1.0f / HH) - mean * mean;
        const float rstd = rsqrtf(var + 1e-5f);
        const float mk = mask[b * SS + s];

#pragma unroll
        for (int i = 0; i < 24; i++) {
            float v = (x[i] - mean) * rstd * gv[i] + bev[i];
            racc[i] += fmaxf(v, 0.0f) * mk;
        }
    }

#pragma unroll
    for (int i = 0; i < 6; i++) {
#pragma unroll
        for (int j = 0; j < 4; j++) {
            int c = i * 128 + lane * 4 + j;
            atomicAdd(&accum[c], racc[i * 4 + j]);
        }
    }
    __syncthreads();
    for (int c = tid; c < HH; c += 256)
        atomicAdd(&g_rbar[b * HH + c], accum[c]);
}

// ===========================================================================
// Kernel: gemv2 split-K x8. grid (3, BB, 8). Partial dot into g_comb (atomic).
// ===========================================================================
__global__ __launch_bounds__(256) void gemv2_kernel(
    const int* __restrict__ lang,
    const float* __restrict__ W2)
{
    const int b = blockIdx.y;
    const int z = blockIdx.z;
    const int n = blockIdx.x * 256 + threadIdx.x;
    const int tid = threadIdx.x;
    const int kb = z * 96;
    __shared__ float tvec[96];

    if (tid < 96) tvec[tid] = g_rbar[b * HH + kb + tid];
    __syncthreads();

    const int l = lang[b];
    const float invD = 1.0f / (g_msum[b] + 1e-10f);
    const float* __restrict__ W2l = W2 + (size_t)l * HH * HH + (size_t)kb * HH;

    float acc = 0.0f;
#pragma unroll 8
    for (int h = 0; h < 96; h++)
        acc += tvec[h] * W2l[(size_t)h * HH + n];

    atomicAdd(&g_comb[b * (HH + TT) + n], acc * invD);
}

// ===========================================================================
// Kernel: fuse split-K x7. grid (2, BB, 7). 868 = 7*124.
// ===========================================================================
__global__ __launch_bounds__(256) void fuse_kernel(const float* __restrict__ Wf)
{
    const int b = blockIdx.y;
    const int z = blockIdx.z;
    const int n = blockIdx.x * 256 + threadIdx.x;
    const int tid = threadIdx.x;
    const int ib = z * 124;
    __shared__ float comb[124];

    if (tid < 124) comb[tid] = g_comb[b * (HH + TT) + ib + tid];
    __syncthreads();

    float f = 0.0f;
#pragma unroll 4
    for (int i = 0; i < 124; i++)
        f += comb[i] * Wf[(size_t)(ib + i) * THH + n];

    atomicAdd(&g_fused[b * THH + n], f);
}

// ===========================================================================
// Kernel: final LN + relu. grid BB, block 512.
// ===========================================================================
__global__ __launch_bounds__(512) void final_ln_kernel(
    const float* __restrict__ gf,
    const float* __restrict__ bef,
    float* __restrict__ out)
{
    const int b = blockIdx.x;
    const int tid = threadIdx.x;
    const int lane = tid & 31;
    const int warp = tid >> 5;
    __shared__ float red[32];

    const float f = g_fused[b * THH + tid];

    float sum = f, sq = f * f;
#pragma unroll
    for (int o = 16; o > 0; o >>= 1) {
        sum += __shfl_xor_sync(0xffffffffu, sum, o);
        sq  += __shfl_xor_sync(0xffffffffu, sq, o);
    }
    if (lane == 0) { red[warp] = sum; red[warp + 16] = sq; }
    __syncthreads();
    if (tid < 32) {
        float v = (tid < 16) ? red[tid] : 0.0f;
        float v2 = (tid < 16) ? red[tid + 16] : 0.0f;
#pragma unroll
        for (int o = 8; o > 0; o >>= 1) {
            v  += __shfl_xor_sync(0xffffffffu, v, o);
            v2 += __shfl_xor_sync(0xffffffffu, v2, o);
        }
        if (tid == 0) { red[0] = v; red[1] = v2; }
    }
    __syncthreads();
    const float mean = red[0] * (1.0f / THH);
    const float var = red[1] * (1.0f / THH) - mean * mean;
    const float rstd = rsqrtf(var + 1e-5f);

    float o = (f - mean) * rstd * gf[tid] + bef[tid];
    out[b * THH + tid] = fmaxf(o, 0.0f);
}

// ===========================================================================
extern "C" void kernel_launch(void* const* d_in, const int* in_sizes, int n_in,
                              void* d_out, int out_size)
{
    const float* seq  = (const float*)d_in[0];
    const float* mask = (const float*)d_in[1];
    const int*   lang = (const int*)d_in[2];
    const float* lda  = (const float*)d_in[3];
    const float* W1   = (const float*)d_in[4];
    const float* b1   = (const float*)d_in[5];
    const float* g1   = (const float*)d_in[6];
    const float* be1  = (const float*)d_in[7];
    const float* W2   = (const float*)d_in[8];
    const float* b2   = (const float*)d_in[9];
    const float* Wf   = (const float*)d_in[10];
    const float* bf   = (const float*)d_in[11];
    const float* gf   = (const float*)d_in[12];
    const float* bef  = (const float*)d_in[13];
    float* out = (float*)d_out;

    (void)in_sizes; (void)n_in; (void)out_size;

    init_kernel<<<BB, 256>>>(mask, lang, b2, lda, bf);
    w1t_prep_kernel<<<dim3(HH / 32, HH / 32, LL), dim3(32, 8)>>>(W1);
    gemm1_mma_kernel<<<dim3(HH / 128, (BB * SS) / 128), 256>>>(seq, lang, b1);
    ln_relu_pool_kernel<<<BB * 8, 256>>>(mask, lang, g1, be1);
    gemv2_kernel<<<dim3(3, BB, 8), 256>>>(lang, W2);
    fuse_kernel<<<dim3(2, BB, 7), 256>>>(Wf);
    final_ln_kernel<<<BB, 512>>>(gf, bef, out);
}

// round 10
// speedup vs baseline: 3.1112x; 1.1240x over previous
#include <cuda_runtime.h>
#include <cuda_bf16.h>
#include <cstdint>

// Problem constants
#define BB 32
#define SS 512
#define HH 768
#define TT 100
#define THH 512
#define LL 5

// Scratch (static device globals — no allocation)
__device__ float g_scratch[BB * SS * HH];   // GEMM1 output: 50.3 MB
__device__ float g_rbar[BB * HH];
__device__ float g_msum[BB];
__device__ float g_comb[BB * (HH + TT)];
__device__ float g_fused[BB * THH];
__device__ __align__(16) __nv_bfloat16 g_w1t_hi[LL * HH * HH];  // W1^T hi, [L][N][K]
__device__ __align__(16) __nv_bfloat16 g_w1t_lo[LL * HH * HH];  // W1^T lo
__device__ __align__(16) __nv_bfloat16 g_a_hi[BB * SS * HH];    // seq hi, [M][K]
__device__ __align__(16) __nv_bfloat16 g_a_lo[BB * SS * HH];    // seq lo

// ---------------------------------------------------------------------------
// mma.sync m16n8k16 bf16 + ldmatrix + cp.async (legacy, base-sm_100-legal)
// ---------------------------------------------------------------------------
__device__ __forceinline__ void mma_bf16(float* c, const uint32_t* a, const uint32_t* b) {
    asm volatile(
        "mma.sync.aligned.m16n8k16.row.col.f32.bf16.bf16.f32 "
        "{%0,%1,%2,%3}, {%4,%5,%6,%7}, {%8,%9}, {%0,%1,%2,%3};"
        : "+f"(c[0]), "+f"(c[1]), "+f"(c[2]), "+f"(c[3])
        : "r"(a[0]), "r"(a[1]), "r"(a[2]), "r"(a[3]), "r"(b[0]), "r"(b[1]));
}
__device__ __forceinline__ void ldsm_x4(uint32_t* r, uint32_t saddr) {
    asm volatile(
        "ldmatrix.sync.aligned.m8n8.x4.shared.b16 {%0,%1,%2,%3}, [%4];"
        : "=r"(r[0]), "=r"(r[1]), "=r"(r[2]), "=r"(r[3]) : "r"(saddr));
}
__device__ __forceinline__ uint32_t smem_u32(const void* p) {
    uint32_t a;
    asm("{ .reg .u64 t; cvta.to.shared.u64 t, %1; cvt.u32.u64 %0, t; }"
        : "=r"(a) : "l"(p));
    return a;
}
__device__ __forceinline__ void cp_async16(uint32_t dst, const void* src) {
    asm volatile("cp.async.cg.shared.global [%0], [%1], 16;"
                 :: "r"(dst), "l"(src));
}
#define CP_COMMIT() asm volatile("cp.async.commit_group;")
#define CP_WAIT1()  asm volatile("cp.async.wait_group 1;")

// ===========================================================================
// Kernel: init — zero rbar, mask sums, seed comb (bias+lda) and fused (bf)
// ===========================================================================
__global__ __launch_bounds__(256) void init_kernel(
    const float* __restrict__ mask, const int* __restrict__ lang,
    const float* __restrict__ b2, const float* __restrict__ lda,
    const float* __restrict__ bf)
{
    const int b = blockIdx.x;
    const int tid = threadIdx.x;
    const int lane = tid & 31;
    const int warp = tid >> 5;
    __shared__ float red[8];
    __shared__ float sh_m;

    for (int c = tid; c < HH; c += 256) g_rbar[b * HH + c] = 0.0f;

    float ms = 0.0f;
    for (int s = tid; s < SS; s += 256) ms += mask[b * SS + s];
#pragma unroll
    for (int o = 16; o > 0; o >>= 1) ms += __shfl_xor_sync(0xffffffffu, ms, o);
    if (lane == 0) red[warp] = ms;
    __syncthreads();
    if (tid == 0) {
        float v = 0.0f;
#pragma unroll
        for (int i = 0; i < 8; i++) v += red[i];
        g_msum[b] = v;
        sh_m = v;
    }
    __syncthreads();

    const int l = lang[b];
    const float Mtot = sh_m;
    const float invD = 1.0f / (Mtot + 1e-10f);
    for (int n = tid; n < HH; n += 256)
        g_comb[b * (HH + TT) + n] = Mtot * b2[l * HH + n] * invD;
    for (int i = tid; i < TT; i += 256)
        g_comb[b * (HH + TT) + HH + i] = lda[b * TT + i];
    for (int n = tid; n < THH; n += 256)
        g_fused[b * THH + n] = bf[n];
}

// ===========================================================================
// Kernel: split seq -> bf16 hi/lo. grid 12288, block 256, 1 float4/thread.
// ===========================================================================
__global__ __launch_bounds__(256) void a_prep_kernel(const float* __restrict__ seq)
{
    const int i = blockIdx.x * 256 + threadIdx.x;   // float4 index
    float4 v = *reinterpret_cast<const float4*>(seq + (size_t)i * 4);
    const float x[4] = {v.x, v.y, v.z, v.w};
    uint32_t h[2], lo[2];
#pragma unroll
    for (int j = 0; j < 2; j++) {
        __nv_bfloat16 h0 = __float2bfloat16(x[2 * j]);
        __nv_bfloat16 h1 = __float2bfloat16(x[2 * j + 1]);
        __nv_bfloat16 l0 = __float2bfloat16(x[2 * j] - __bfloat162float(h0));
        __nv_bfloat16 l1 = __float2bfloat16(x[2 * j + 1] - __bfloat162float(h1));
        h[j]  = ((uint32_t)__bfloat16_as_ushort(h1) << 16) | __bfloat16_as_ushort(h0);
        lo[j] = ((uint32_t)__bfloat16_as_ushort(l1) << 16) | __bfloat16_as_ushort(l0);
    }
    *reinterpret_cast<uint2*>(g_a_hi + (size_t)i * 4) = make_uint2(h[0], h[1]);
    *reinterpret_cast<uint2*>(g_a_lo + (size_t)i * 4) = make_uint2(lo[0], lo[1]);
}

// ===========================================================================
// Kernel: W1 -> W1^T split to bf16 hi/lo. grid (24,24,L), block (32,8)
// ===========================================================================
__global__ __launch_bounds__(256) void w1t_prep_kernel(const float* __restrict__ W1)
{
    __shared__ float tile[32][33];
    const int l = blockIdx.z;
    const int n0 = blockIdx.x * 32;
    const int k0 = blockIdx.y * 32;
    const float* __restrict__ W = W1 + (size_t)l * HH * HH;
#pragma unroll
    for (int j = 0; j < 4; j++) {
        int k = k0 + threadIdx.y + j * 8;
        tile[threadIdx.y + j * 8][threadIdx.x] = W[(size_t)k * HH + n0 + threadIdx.x];
    }
    __syncthreads();
#pragma unroll
    for (int j = 0; j < 4; j++) {
        int n = n0 + threadIdx.y + j * 8;
        float v = tile[threadIdx.x][threadIdx.y + j * 8];
        __nv_bfloat16 h = __float2bfloat16(v);
        __nv_bfloat16 lo = __float2bfloat16(v - __bfloat162float(h));
        size_t o = (size_t)l * HH * HH + (size_t)n * HH + k0 + threadIdx.x;
        g_w1t_hi[o] = h;
        g_w1t_lo[o] = lo;
    }
}

// ===========================================================================
// Kernel: GEMM1 via mma.sync bf16-split + ldmatrix + cp.async double-buffer.
// CTA tile 128x128, BK=32, 8 warps (2m x 4n), warp tile 64x32.
// Smem: 2 stages x 4 tiles x (128 rows x 80B) = 80KB dynamic.
// ===========================================================================
#define BKP 40            // padded K stride in bf16 elems (80B rows)
#define TILE_BYTES 10240  // 128 * 80
#define STAGE_BYTES 40960
#define NCH (HH / 32)     // 24

__global__ __launch_bounds__(256) void gemm1_mma_kernel(
    const int* __restrict__ lang,
    const float* __restrict__ b1)
{
    extern __shared__ char smem[];
    const uint32_t sbase = smem_u32(smem);

    const int tid = threadIdx.x;
    const int wid = tid >> 5;
    const int lane = tid & 31;
    const int g = lane >> 2;
    const int tg = lane & 3;

    const int n0 = blockIdx.x * 128;
    const int m0 = blockIdx.y * 128;
    const int b = m0 / SS;
    const int l = lang[b];

    const int wm = (wid & 1) * 64;
    const int wn = (wid >> 1) * 32;

    // ldmatrix per-lane source coords
    const int a_r = (lane & 7) + 8 * ((lane >> 3) & 1);
    const int a_c = 8 * (lane >> 4);
    const int b_r = (lane & 7) + 8 * (lane >> 4);
    const int b_c = 8 * ((lane >> 3) & 1);

    const __nv_bfloat16* __restrict__ Ah = g_a_hi + (size_t)m0 * HH;
    const __nv_bfloat16* __restrict__ Al = g_a_lo + (size_t)m0 * HH;
    const __nv_bfloat16* __restrict__ Bh = g_w1t_hi + (size_t)l * HH * HH + (size_t)n0 * HH;
    const __nv_bfloat16* __restrict__ Bl = g_w1t_lo + (size_t)l * HH * HH + (size_t)n0 * HH;

    // cp.async coords: per tile, 512 x 16B chunks; 2 per thread.
    const int ld_row0 = tid >> 2;              // rows 0..63   (j=0)
    const int ld_row1 = 64 + (tid >> 2);       // rows 64..127 (j=1)
    const int ld_c = (tid & 3) * 8;            // bf16 elem offset (16B chunk)

    float acc[4][4][4];
#pragma unroll
    for (int mi = 0; mi < 4; mi++)
#pragma unroll
        for (int ni = 0; ni < 4; ni++)
#pragma unroll
            for (int r = 0; r < 4; r++) acc[mi][ni][r] = 0.0f;

    // ---- issue helper (macro to keep regs simple) ----
#define ISSUE_CHUNK(ST, K0)                                                     \
    do {                                                                        \
        const uint32_t sb_ = sbase + (ST) * STAGE_BYTES;                        \
        cp_async16(sb_ + 0 * TILE_BYTES + ld_row0 * 80 + ld_c * 2,              \
                   Ah + (size_t)ld_row0 * HH + (K0) + ld_c);                    \
        cp_async16(sb_ + 0 * TILE_BYTES + ld_row1 * 80 + ld_c * 2,              \
                   Ah + (size_t)ld_row1 * HH + (K0) + ld_c);                    \
        cp_async16(sb_ + 1 * TILE_BYTES + ld_row0 * 80 + ld_c * 2,              \
                   Al + (size_t)ld_row0 * HH + (K0) + ld_c);                    \
        cp_async16(sb_ + 1 * TILE_BYTES + ld_row1 * 80 + ld_c * 2,              \
                   Al + (size_t)ld_row1 * HH + (K0) + ld_c);                    \
        cp_async16(sb_ + 2 * TILE_BYTES + ld_row0 * 80 + ld_c * 2,              \
                   Bh + (size_t)ld_row0 * HH + (K0) + ld_c);                    \
        cp_async16(sb_ + 2 * TILE_BYTES + ld_row1 * 80 + ld_c * 2,              \
                   Bh + (size_t)ld_row1 * HH + (K0) + ld_c);                    \
        cp_async16(sb_ + 3 * TILE_BYTES + ld_row0 * 80 + ld_c * 2,              \
                   Bl + (size_t)ld_row0 * HH + (K0) + ld_c);                    \
        cp_async16(sb_ + 3 * TILE_BYTES + ld_row1 * 80 + ld_c * 2,              \
                   Bl + (size_t)ld_row1 * HH + (K0) + ld_c);                    \
    } while (0)

    // ---- prologue: fill both stages ----
    ISSUE_CHUNK(0, 0);
    CP_COMMIT();
    ISSUE_CHUNK(1, 32);
    CP_COMMIT();

    for (int it = 0; it < NCH; ++it) {
        const int st = it & 1;
        const uint32_t as_hi = sbase + st * STAGE_BYTES;
        const uint32_t as_lo = as_hi + TILE_BYTES;
        const uint32_t bs_hi = as_hi + 2 * TILE_BYTES;
        const uint32_t bs_lo = as_hi + 3 * TILE_BYTES;

        CP_WAIT1();
        __syncthreads();

        // ---- compute: 2 k16 steps, ldmatrix-fed ----
#pragma unroll
        for (int ks = 0; ks < 2; ks++) {
            const int kk = ks * 16;

            uint32_t bh[2][4], bl[2][4];
#pragma unroll
            for (int p = 0; p < 2; p++) {
                uint32_t off = (uint32_t)((wn + p * 16 + b_r) * 80 + (kk + b_c) * 2);
                ldsm_x4(bh[p], bs_hi + off);
                ldsm_x4(bl[p], bs_lo + off);
            }

            uint32_t ah[4][4];
#pragma unroll
            for (int mi = 0; mi < 4; mi++) {
                uint32_t off = (uint32_t)((wm + mi * 16 + a_r) * 80 + (kk + a_c) * 2);
                ldsm_x4(ah[mi], as_hi + off);
            }
#pragma unroll
            for (int mi = 0; mi < 4; mi++) {
#pragma unroll
                for (int ni = 0; ni < 4; ni++) {
                    mma_bf16(acc[mi][ni], ah[mi], &bh[ni >> 1][(ni & 1) * 2]);
                    mma_bf16(acc[mi][ni], ah[mi], &bl[ni >> 1][(ni & 1) * 2]);
                }
            }
#pragma unroll
            for (int mi = 0; mi < 4; mi++) {
                uint32_t al4[4];
                uint32_t off = (uint32_t)((wm + mi * 16 + a_r) * 80 + (kk + a_c) * 2);
                ldsm_x4(al4, as_lo + off);
#pragma unroll
                for (int ni = 0; ni < 4; ni++)
                    mma_bf16(acc[mi][ni], al4, &bh[ni >> 1][(ni & 1) * 2]);
            }
        }
        __syncthreads();

        // ---- refill this stage with chunk it+2 ----
        if (it + 2 < NCH)
            ISSUE_CHUNK(st, (it + 2) * 32);
        CP_COMMIT();
    }
#undef ISSUE_CHUNK

    // ---- epilogue: add bias, write to g_scratch ----
    const float* __restrict__ bp = b1 + (size_t)l * HH;
#pragma unroll
    for (int ni = 0; ni < 4; ni++) {
        int n = n0 + wn + ni * 8 + tg * 2;
        float2 bv = *reinterpret_cast<const float2*>(bp + n);
#pragma unroll
        for (int mi = 0; mi < 4; mi++) {
            int mA = m0 + wm + mi * 16 + g;
            float2 o0, o1;
            o0.x = acc[mi][ni][0] + bv.x;
            o0.y = acc[mi][ni][1] + bv.y;
            o1.x = acc[mi][ni][2] + bv.x;
            o1.y = acc[mi][ni][3] + bv.y;
            *reinterpret_cast<float2*>(g_scratch + (size_t)mA * HH + n) = o0;
            *reinterpret_cast<float2*>(g_scratch + (size_t)(mA + 8) * HH + n) = o1;
        }
    }
}

// ===========================================================================
// Kernel: LN + ReLU + masked pool
// ===========================================================================
__global__ __launch_bounds__(256) void ln_relu_pool_kernel(
    const float* __restrict__ mask,
    const int* __restrict__ lang,
    const float* __restrict__ g1,
    const float* __restrict__ be1)
{
    __shared__ float accum[HH];
    const int blk = blockIdx.x;
    const int b = blk >> 3;
    const int s_base = (blk & 7) * 64;
    const int tid = threadIdx.x;
    const int w = tid >> 5;
    const int lane = tid & 31;

    for (int c = tid; c < HH; c += 256) accum[c] = 0.0f;
    __syncthreads();

    const int l = lang[b];
    const float* __restrict__ g = g1 + (size_t)l * HH;
    const float* __restrict__ be = be1 + (size_t)l * HH;

    float gv[24], bev[24];
#pragma unroll
    for (int i = 0; i < 6; i++) {
        float4 gg = *reinterpret_cast<const float4*>(g + i * 128 + lane * 4);
        float4 bb = *reinterpret_cast<const float4*>(be + i * 128 + lane * 4);
        gv[i * 4 + 0] = gg.x; gv[i * 4 + 1] = gg.y;
        gv[i * 4 + 2] = gg.z; gv[i * 4 + 3] = gg.w;
        bev[i * 4 + 0] = bb.x; bev[i * 4 + 1] = bb.y;
        bev[i * 4 + 2] = bb.z; bev[i * 4 + 3] = bb.w;
    }

    float racc[24];
#pragma unroll
    for (int i = 0; i < 24; i++) racc[i] = 0.0f;

    for (int r = 0; r < 8; r++) {
        const int s = s_base + w * 8 + r;
        const float* __restrict__ row = g_scratch + ((size_t)b * SS + s) * HH;

        float x[24];
        float sum = 0.0f, sq = 0.0f;
#pragma unroll
        for (int i = 0; i < 6; i++) {
            float4 v = *reinterpret_cast<const float4*>(row + i * 128 + lane * 4);
            x[i * 4 + 0] = v.x; x[i * 4 + 1] = v.y;
            x[i * 4 + 2] = v.z; x[i * 4 + 3] = v.w;
            sum += v.x + v.y + v.z + v.w;
            sq += v.x * v.x + v.y * v.y + v.z * v.z + v.w * v.w;
        }
#pragma unroll
        for (int o = 16; o > 0; o >>= 1) {
            sum += __shfl_xor_sync(0xffffffffu, sum, o);
            sq  += __shfl_xor_sync(0xffffffffu, sq, o);
        }
        const float mean = sum * (1.0f / HH);
        const float var = sq * (1.0f / HH) - mean * mean;
        const float rstd = rsqrtf(var + 1e-5f);
        const float mk = mask[b * SS + s];

#pragma unroll
        for (int i = 0; i < 24; i++) {
            float v = (x[i] - mean) * rstd * gv[i] + bev[i];
            racc[i] += fmaxf(v, 0.0f) * mk;
        }
    }

#pragma unroll
    for (int i = 0; i < 6; i++) {
#pragma unroll
        for (int j = 0; j < 4; j++) {
            int c = i * 128 + lane * 4 + j;
            atomicAdd(&accum[c], racc[i * 4 + j]);
        }
    }
    __syncthreads();
    for (int c = tid; c < HH; c += 256)
        atomicAdd(&g_rbar[b * HH + c], accum[c]);
}

// ===========================================================================
// Kernel: gemv2 split-K x8. grid (3, BB, 8). Partial dot into g_comb (atomic).
// ===========================================================================
__global__ __launch_bounds__(256) void gemv2_kernel(
    const int* __restrict__ lang,
    const float* __restrict__ W2)
{
    const int b = blockIdx.y;
    const int z = blockIdx.z;
    const int n = blockIdx.x * 256 + threadIdx.x;
    const int tid = threadIdx.x;
    const int kb = z * 96;
    __shared__ float tvec[96];

    if (tid < 96) tvec[tid] = g_rbar[b * HH + kb + tid];
    __syncthreads();

    const int l = lang[b];
    const float invD = 1.0f / (g_msum[b] + 1e-10f);
    const float* __restrict__ W2l = W2 + (size_t)l * HH * HH + (size_t)kb * HH;

    float acc = 0.0f;
#pragma unroll 8
    for (int h = 0; h < 96; h++)
        acc += tvec[h] * W2l[(size_t)h * HH + n];

    atomicAdd(&g_comb[b * (HH + TT) + n], acc * invD);
}

// ===========================================================================
// Kernel: fuse split-K x7. grid (2, BB, 7). 868 = 7*124.
// ===========================================================================
__global__ __launch_bounds__(256) void fuse_kernel(const float* __restrict__ Wf)
{
    const int b = blockIdx.y;
    const int z = blockIdx.z;
    const int n = blockIdx.x * 256 + threadIdx.x;
    const int tid = threadIdx.x;
    const int ib = z * 124;
    __shared__ float comb[124];

    if (tid < 124) comb[tid] = g_comb[b * (HH + TT) + ib + tid];
    __syncthreads();

    float f = 0.0f;
#pragma unroll 4
    for (int i = 0; i < 124; i++)
        f += comb[i] * Wf[(size_t)(ib + i) * THH + n];

    atomicAdd(&g_fused[b * THH + n], f);
}

// ===========================================================================
// Kernel: final LN + relu. grid BB, block 512.
// ===========================================================================
__global__ __launch_bounds__(512) void final_ln_kernel(
    const float* __restrict__ gf,
    const float* __restrict__ bef,
    float* __restrict__ out)
{
    const int b = blockIdx.x;
    const int tid = threadIdx.x;
    const int lane = tid & 31;
    const int warp = tid >> 5;
    __shared__ float red[32];

    const float f = g_fused[b * THH + tid];

    float sum = f, sq = f * f;
#pragma unroll
    for (int o = 16; o > 0; o >>= 1) {
        sum += __shfl_xor_sync(0xffffffffu, sum, o);
        sq  += __shfl_xor_sync(0xffffffffu, sq, o);
    }
    if (lane == 0) { red[warp] = sum; red[warp + 16] = sq; }
    __syncthreads();
    if (tid < 32) {
        float v = (tid < 16) ? red[tid] : 0.0f;
        float v2 = (tid < 16) ? red[tid + 16] : 0.0f;
#pragma unroll
        for (int o = 8; o > 0; o >>= 1) {
            v  += __shfl_xor_sync(0xffffffffu, v, o);
            v2 += __shfl_xor_sync(0xffffffffu, v2, o);
        }
        if (tid == 0) { red[0] = v; red[1] = v2; }
    }
    __syncthreads();
    const float mean = red[0] * (1.0f / THH);
    const float var = red[1] * (1.0f / THH) - mean * mean;
    const float rstd = rsqrtf(var + 1e-5f);

    float o = (f - mean) * rstd * gf[tid] + bef[tid];
    out[b * THH + tid] = fmaxf(o, 0.0f);
}

// ===========================================================================
extern "C" void kernel_launch(void* const* d_in, const int* in_sizes, int n_in,
                              void* d_out, int out_size)
{
    const float* seq  = (const float*)d_in[0];
    const float* mask = (const float*)d_in[1];
    const int*   lang = (const int*)d_in[2];
    const float* lda  = (const float*)d_in[3];
    const float* W1   = (const float*)d_in[4];
    const float* b1   = (const float*)d_in[5];
    const float* g1   = (const float*)d_in[6];
    const float* be1  = (const float*)d_in[7];
    const float* W2   = (const float*)d_in[8];
    const float* b2   = (const float*)d_in[9];
    const float* Wf   = (const float*)d_in[10];
    const float* bf   = (const float*)d_in[11];
    const float* gf   = (const float*)d_in[12];
    const float* bef  = (const float*)d_in[13];
    float* out = (float*)d_out;

    (void)in_sizes; (void)n_in; (void)out_size;

    cudaFuncSetAttribute(gemm1_mma_kernel,
                         cudaFuncAttributeMaxDynamicSharedMemorySize, 2 * STAGE_BYTES);

    init_kernel<<<BB, 256>>>(mask, lang, b2, lda, bf);
    a_prep_kernel<<<(BB * SS * HH) / 1024, 256>>>(seq);
    w1t_prep_kernel<<<dim3(HH / 32, HH / 32, LL), dim3(32, 8)>>>(W1);
    gemm1_mma_kernel<<<dim3(HH / 128, (BB * SS) / 128), 256, 2 * STAGE_BYTES>>>(lang, b1);
    ln_relu_pool_kernel<<<BB * 8, 256>>>(mask, lang, g1, be1);
    gemv2_kernel<<<dim3(3, BB, 8), 256>>>(lang, W2);
    fuse_kernel<<<dim3(2, BB, 7), 256>>>(Wf);
    final_ln_kernel<<<BB, 512>>>(gf, bef, out);
}